// round 2
// baseline (speedup 1.0000x reference)
#include <cuda_runtime.h>
#include <cstdint>
#include <cstddef>

// ---------------- problem constants ----------------
#define BATCH 128
#define NAT   48
#define NBD   96
#define HID   200
#define AFD   39
#define BFD   50      // ATOM_FDIM + BOND_FDIM
#define PL    1000

// ---------------- device scratch (no allocs allowed) ----------------
__device__ float g_binput[BATCH * NBD * HID];
__device__ float g_message[BATCH * NBD * HID];
__device__ float g_nei[BATCH * NBD * HID];
__device__ float g_atomh[BATCH * NAT * HID];
__device__ float g_emb[BATCH * HID];
__device__ float g_prot[BATCH * 50 * PL];     // (B, 50, L)
__device__ float g_conv0[BATCH * 96 * PL];    // (B, 96, L)
__device__ float g_conv1[BATCH * 128 * PL];   // (B, 128, L)
__device__ int   g_pvec[BATCH * 200];         // float bits, relu>=0 so int-max works
__device__ float g_fc1o[BATCH * 200];
__device__ float g_fc2o[BATCH * 100];

// ---------------- init ----------------
__global__ void k_init() {
    int i = blockIdx.x * blockDim.x + threadIdx.x;
    if (i < BATCH * 200) g_pvec[i] = 0;
}

// ---------------- MPNN ----------------
// binput = fbonds @ W_i ; message = relu(binput)
__global__ __launch_bounds__(256) void k_binput(const float* __restrict__ fb,
                                                const float* __restrict__ Wi) {
    int row = blockIdx.x;            // 0 .. B*NBD-1
    int t = threadIdx.x;
    __shared__ float sx[BFD];
    if (t < BFD) sx[t] = fb[row * BFD + t];
    __syncthreads();
    if (t < HID) {
        float acc = 0.f;
#pragma unroll
        for (int k = 0; k < BFD; k++) acc = fmaf(sx[k], Wi[k * HID + t], acc);
        g_binput[row * HID + t] = acc;
        g_message[row * HID + t] = fmaxf(acc, 0.f);
    }
}

// nei[i,:] = sum_j message[mol, bgraph[i,j], :]
__global__ __launch_bounds__(256) void k_gather_bonds(const int* __restrict__ bg) {
    int i = blockIdx.x;              // bond row
    __shared__ int si[6];
    int t = threadIdx.x;
    if (t < 6) si[t] = bg[i * 6 + t];
    __syncthreads();
    if (t < HID) {
        const float* base = g_message + (size_t)(i / NBD) * NBD * HID;
        float s = 0.f;
#pragma unroll
        for (int j = 0; j < 6; j++) s += base[si[j] * HID + t];
        g_nei[i * HID + t] = s;
    }
}

// message = relu(binput + nei @ W_h)
__global__ __launch_bounds__(256) void k_msg_update(const float* __restrict__ Wh) {
    int row = blockIdx.x;
    int t = threadIdx.x;
    __shared__ float sx[HID];
    if (t < HID) sx[t] = g_nei[row * HID + t];
    __syncthreads();
    if (t < HID) {
        float acc = 0.f;
#pragma unroll 4
        for (int k = 0; k < HID; k++) acc = fmaf(sx[k], Wh[k * HID + t], acc);
        g_message[row * HID + t] = fmaxf(g_binput[row * HID + t] + acc, 0.f);
    }
}

// atom_h = relu(concat(fa, gather-sum(message via agraph)) @ W_o + b)
__global__ __launch_bounds__(256) void k_atom(const float* __restrict__ fa,
                                              const int* __restrict__ ag,
                                              const float* __restrict__ Wo,
                                              const float* __restrict__ Wob) {
    int a = blockIdx.x;              // 0 .. B*NAT-1
    int b = a / NAT;
    int t = threadIdx.x;
    __shared__ float sx[AFD + HID];  // 239
    __shared__ int si[6];
    if (t < 6) si[t] = ag[a * 6 + t];
    if (t >= 64 && t < 64 + AFD) sx[t - 64] = fa[a * AFD + (t - 64)];
    __syncthreads();
    if (t < HID) {
        const float* base = g_message + (size_t)b * NBD * HID;
        float s = 0.f;
#pragma unroll
        for (int j = 0; j < 6; j++) s += base[si[j] * HID + t];
        sx[AFD + t] = s;
    }
    __syncthreads();
    if (t < HID) {
        float acc = Wob[t];
#pragma unroll 4
        for (int k = 0; k < AFD + HID; k++) acc = fmaf(sx[k], Wo[k * HID + t], acc);
        g_atomh[a * HID + t] = fmaxf(acc, 0.f);
    }
}

// embeddings = mean over atoms (deterministic, no atomics)
__global__ void k_mean() {
    int b = blockIdx.x;
    int t = threadIdx.x;
    if (t < HID) {
        float s = 0.f;
        for (int a = 0; a < NAT; a++) s += g_atomh[(b * NAT + a) * HID + t];
        g_emb[b * HID + t] = s * (1.f / 48.f);
    }
}

// ---------------- protein tower ----------------
__global__ void k_embed(const int* __restrict__ seq, const float* __restrict__ ep) {
    int idx = blockIdx.x * blockDim.x + threadIdx.x;
    if (idx < BATCH * 50 * PL) {
        int l = idx % PL;
        int bc = idx / PL;
        int c = bc % 50;
        int b = bc / 50;
        g_prot[idx] = ep[seq[b * PL + l] * 50 + c];
    }
}

// register-blocked direct conv1d ("same" padding) + relu; optionally fused global max
template <int CIN, int COUT, int KS, bool FUSE_MAX>
__global__ __launch_bounds__(256) void k_conv(const float* __restrict__ in,
                                              const float* __restrict__ wt,
                                              const float* __restrict__ bias,
                                              float* __restrict__ out,
                                              int* __restrict__ pvec) {
    constexpr int TL = 128, LR = 4, OCR = 2, OCS = 16, SPITCH = 136;
    constexpr int PAD = KS / 2;
    constexpr int NV4 = (LR + KS - 1 + 3) / 4;
    extern __shared__ float sm[];
    float* s_in = sm;                       // CIN * SPITCH
    float* s_w  = sm + CIN * SPITCH;        // OCS * CIN * KS
    const int l0 = blockIdx.x * TL;
    const int b  = blockIdx.y;
    const int tid = threadIdx.x;

    for (int e = tid; e < CIN * SPITCH; e += 256) {
        int cin = e / SPITCH;
        int p   = e - cin * SPITCH;
        int gl  = l0 + p - PAD;
        float v = 0.f;
        if (gl >= 0 && gl < PL && p < TL + KS - 1)
            v = in[((size_t)b * CIN + cin) * PL + gl];
        s_in[e] = v;
    }

    const int pl = tid & 31;   // position lane (warp = one oc-group)
    const int og = tid >> 5;   // oc group 0..7
    const int p0 = pl * LR;

    for (int ocb = 0; ocb < COUT; ocb += OCS) {
        __syncthreads();
        for (int e = tid; e < OCS * CIN * KS; e += 256) {
            int j = e / (CIN * KS);
            int r = e - j * (CIN * KS);
            int oc = ocb + j;
            s_w[e] = (oc < COUT) ? wt[(size_t)oc * CIN * KS + r] : 0.f;
        }
        __syncthreads();

        float acc[OCR][LR];
#pragma unroll
        for (int r = 0; r < OCR; r++)
#pragma unroll
            for (int l = 0; l < LR; l++) acc[r][l] = 0.f;

#pragma unroll 2
        for (int cin = 0; cin < CIN; cin++) {
            float xr[NV4 * 4];
            const float4* rp = reinterpret_cast<const float4*>(s_in + cin * SPITCH + p0);
#pragma unroll
            for (int v = 0; v < NV4; v++) {
                float4 q = rp[v];
                xr[v * 4 + 0] = q.x; xr[v * 4 + 1] = q.y;
                xr[v * 4 + 2] = q.z; xr[v * 4 + 3] = q.w;
            }
#pragma unroll
            for (int r = 0; r < OCR; r++) {
                const float* wp = s_w + ((og * OCR + r) * CIN + cin) * KS;
#pragma unroll
                for (int k = 0; k < KS; k++) {
                    float wv = wp[k];
#pragma unroll
                    for (int l = 0; l < LR; l++)
                        acc[r][l] = fmaf(xr[l + k], wv, acc[r][l]);
                }
            }
        }

#pragma unroll
        for (int r = 0; r < OCR; r++) {
            int oc = ocb + og * OCR + r;
            if (oc < COUT) {
                float bz = bias[oc];
                if (FUSE_MAX) {
                    float m = 0.f;
#pragma unroll
                    for (int l = 0; l < LR; l++)
                        if (l0 + p0 + l < PL)
                            m = fmaxf(m, fmaxf(acc[r][l] + bz, 0.f));
#pragma unroll
                    for (int off = 16; off > 0; off >>= 1)
                        m = fmaxf(m, __shfl_xor_sync(0xffffffffu, m, off));
                    if (pl == 0)
                        atomicMax(&pvec[b * COUT + oc], __float_as_int(m));
                } else {
                    if (l0 + p0 < PL) {   // L%4==0 -> whole float4 valid or invalid
                        float4 v;
                        v.x = fmaxf(acc[r][0] + bz, 0.f);
                        v.y = fmaxf(acc[r][1] + bz, 0.f);
                        v.z = fmaxf(acc[r][2] + bz, 0.f);
                        v.w = fmaxf(acc[r][3] + bz, 0.f);
                        *reinterpret_cast<float4*>(out + ((size_t)b * COUT + oc) * PL + l0 + p0) = v;
                    }
                }
            }
        }
    }
}

// ---------------- FC head ----------------
__global__ __launch_bounds__(256) void k_fc0(const float* __restrict__ w,
                                             const float* __restrict__ bias) {
    int b = blockIdx.x;
    int t = threadIdx.x;
    __shared__ float sx[400];
    if (t < 200) {
        sx[t] = g_emb[b * HID + t];
        sx[200 + t] = __int_as_float(g_pvec[b * 200 + t]);
    }
    __syncthreads();
    if (t < 200) {
        float acc = bias[t];
#pragma unroll 4
        for (int k = 0; k < 400; k++) acc = fmaf(sx[k], w[k * 200 + t], acc);
        g_fc1o[b * 200 + t] = fmaxf(acc, 0.f);
    }
}

__global__ __launch_bounds__(256) void k_fc1(const float* __restrict__ w,
                                             const float* __restrict__ bias) {
    int b = blockIdx.x;
    int t = threadIdx.x;
    __shared__ float sx[200];
    if (t < 200) sx[t] = g_fc1o[b * 200 + t];
    __syncthreads();
    if (t < 100) {
        float acc = bias[t];
#pragma unroll 4
        for (int k = 0; k < 200; k++) acc = fmaf(sx[k], w[k * 100 + t], acc);
        g_fc2o[b * 100 + t] = fmaxf(acc, 0.f);
    }
}

__global__ void k_fc2(const float* __restrict__ w, const float* __restrict__ bias,
                      float* __restrict__ out) {
    int b = threadIdx.x;
    if (b < BATCH) {
        float acc = bias[0];
#pragma unroll 4
        for (int k = 0; k < 100; k++) acc = fmaf(g_fc2o[b * 100 + k], w[k], acc);
        out[b] = acc;
    }
}

// ---------------- launch ----------------
extern "C" void kernel_launch(void* const* d_in, const int* in_sizes, int n_in,
                              void* d_out, int out_size) {
    const float* fatoms = (const float*)d_in[0];
    const float* fbonds = (const float*)d_in[1];
    const int*   agraph = (const int*)d_in[2];
    const int*   bgraph = (const int*)d_in[3];
    const int*   pseq   = (const int*)d_in[4];
    const float* Wi  = (const float*)d_in[5];
    const float* Wh  = (const float*)d_in[6];
    const float* Wo  = (const float*)d_in[7];
    const float* Wob = (const float*)d_in[8];
    const float* Epr = (const float*)d_in[9];
    const float* c0w = (const float*)d_in[10]; const float* c0b = (const float*)d_in[11];
    const float* c1w = (const float*)d_in[12]; const float* c1b = (const float*)d_in[13];
    const float* c2w = (const float*)d_in[14]; const float* c2b = (const float*)d_in[15];
    const float* f0w = (const float*)d_in[16]; const float* f0b = (const float*)d_in[17];
    const float* f1w = (const float*)d_in[18]; const float* f1b = (const float*)d_in[19];
    const float* f2w = (const float*)d_in[20]; const float* f2b = (const float*)d_in[21];
    float* out = (float*)d_out;

    void *p_prot, *p_c0, *p_c1, *p_pv;
    cudaGetSymbolAddress(&p_prot, g_prot);
    cudaGetSymbolAddress(&p_c0, g_conv0);
    cudaGetSymbolAddress(&p_c1, g_conv1);
    cudaGetSymbolAddress(&p_pv, g_pvec);

    constexpr int SM0 = (50 * 136 + 16 * 50 * 3) * 4;    // 36.8 KB
    constexpr int SM1 = (96 * 136 + 16 * 96 * 5) * 4;    // 82.9 KB
    constexpr int SM2 = (128 * 136 + 16 * 128 * 7) * 4;  // 127 KB
    cudaFuncSetAttribute((const void*)&k_conv<96, 128, 5, false>,
                         cudaFuncAttributeMaxDynamicSharedMemorySize, SM1);
    cudaFuncSetAttribute((const void*)&k_conv<128, 200, 7, true>,
                         cudaFuncAttributeMaxDynamicSharedMemorySize, SM2);

    k_init<<<(BATCH * 200 + 255) / 256, 256>>>();

    // MPNN chain
    k_binput<<<BATCH * NBD, 256>>>(fbonds, Wi);
    for (int d = 0; d < 2; d++) {
        k_gather_bonds<<<BATCH * NBD, 256>>>(bgraph);
        k_msg_update<<<BATCH * NBD, 256>>>(Wh);
    }
    k_atom<<<BATCH * NAT, 256>>>(fatoms, agraph, Wo, Wob);
    k_mean<<<BATCH, 256>>>();

    // protein tower
    k_embed<<<(BATCH * 50 * PL + 255) / 256, 256>>>(pseq, Epr);
    dim3 cg((PL + 127) / 128, BATCH);
    k_conv<50, 96, 3, false><<<cg, 256, SM0>>>((const float*)p_prot, c0w, c0b, (float*)p_c0, nullptr);
    k_conv<96, 128, 5, false><<<cg, 256, SM1>>>((const float*)p_c0, c1w, c1b, (float*)p_c1, nullptr);
    k_conv<128, 200, 7, true><<<cg, 256, SM2>>>((const float*)p_c1, c2w, c2b, nullptr, (int*)p_pv);

    // FC head
    k_fc0<<<BATCH, 256>>>(f0w, f0b);
    k_fc1<<<BATCH, 256>>>(f1w, f1b);
    k_fc2<<<1, 128>>>(f2w, f2b, out);
}